// round 9
// baseline (speedup 1.0000x reference)
#include <cuda_runtime.h>
#include <cstddef>

// DPLoss: mean over B rows of [ sum_{j<len[i]} (pred[i,j]-log(align[i,j]))^2 / len[i] ]
// B=4096, T=2048, fp32, len ~ U[1,2048].
//
// R9: prefix-only loads (R8's 2x traffic cut: ~34MB) + warp-autonomous rows.
// Exactly one warp per row (4096 warps = 1024 CTAs x 128 thr), no barriers
// or tickets in the hot path. Lanes stride the row prefix in groups of 4
// vec4s with all 8 predicated LDG.128 front-batched (MLP~8/lane). Per-warp
// shuffle reduce -> one RED.ADD; last warp (counter) writes the mean and
// self-resets for CUDA-graph replay.

#define B_ROWS   4096
#define T_VEC4   512                   // float4 per full row
#define NTHREADS 128                   // 4 warps per CTA
#define NCTAS    (B_ROWS / 4)          // 1024 CTAs -> 4096 warps
#define NWARPS   B_ROWS

__device__ float    g_acc   = 0.0f;
__device__ unsigned g_count = 0;

__global__ __launch_bounds__(NTHREADS) void dploss_kernel(
    const float4* __restrict__ pred,
    const float4* __restrict__ align,
    const int* __restrict__ lens,
    float* __restrict__ out)
{
    const int wid  = threadIdx.x >> 5;
    const int lane = threadIdx.x & 31;
    const int row  = blockIdx.x * (NTHREADS / 32) + wid;   // one row per warp

    const int len  = __ldg(lens + row);
    const int nvec = (len + 3) >> 2;                       // float4s needed

    const float4* __restrict__ p = pred  + (size_t)row * T_VEC4;
    const float4* __restrict__ a = align + (size_t)row * T_VEC4;

    float rs = 0.0f;

    // Groups of 4 vec4 per lane (128 vec4 per warp per group). All loads of a
    // group are issued (predicated) before any compute consumes them.
    for (int base = 0; base < nvec; base += 128) {
        float4 pv[4], av[4];
        bool   ok[4];
        #pragma unroll
        for (int m = 0; m < 4; ++m) {
            const int i = base + m * 32 + lane;
            ok[m] = (i < nvec);
            if (ok[m]) { pv[m] = p[i]; av[m] = a[i]; }
        }
        #pragma unroll
        for (int m = 0; m < 4; ++m) {
            if (ok[m]) {
                const int j = (base + m * 32 + lane) << 2;
                float d0 = pv[m].x - __logf(av[m].x);
                float d1 = pv[m].y - __logf(av[m].y);
                float d2 = pv[m].z - __logf(av[m].z);
                float d3 = pv[m].w - __logf(av[m].w);
                if (j + 4 <= len) {                    // full vec4 (common)
                    rs += d0 * d0 + d1 * d1 + d2 * d2 + d3 * d3;
                } else {                               // row's last, partial
                    rs += d0 * d0;
                    if (j + 1 < len) rs += d1 * d1;
                    if (j + 2 < len) rs += d2 * d2;
                    if (j + 3 < len) rs += d3 * d3;
                }
            }
        }
    }

    rs *= __fdividef(1.0f, (float)len);

    // warp reduction
    #pragma unroll
    for (int off = 16; off > 0; off >>= 1)
        rs += __shfl_down_sync(0xFFFFFFFFu, rs, off);

    if (lane == 0) {
        atomicAdd(&g_acc, rs);
        __threadfence();
        unsigned prev = atomicInc(&g_count, NWARPS - 1);
        if (prev == NWARPS - 1) {
            float total = atomicExch(&g_acc, 0.0f);    // read + reset for replay
            *out = total * (1.0f / (float)B_ROWS);
        }
    }
}

extern "C" void kernel_launch(void* const* d_in, const int* in_sizes, int n_in,
                              void* d_out, int out_size)
{
    const float4* pred  = (const float4*)d_in[0];
    const float4* align = (const float4*)d_in[1];
    const int*    lens  = (const int*)d_in[2];
    float* out = (float*)d_out;

    dploss_kernel<<<NCTAS, NTHREADS>>>(pred, align, lens, out);
}